// round 14
// baseline (speedup 1.0000x reference)
#include <cuda_runtime.h>
#include <cuda_fp16.h>
#include <math.h>
#include <stdint.h>

// Problem constants
#define Bn 32
#define CIN 96
#define Tt 288
#define Vv 25
#define Ss 3
#define Cc 96
#define Oo 288
#define VP 28
#define TTc 32
#define NT 9
#define WROW 292         // sYt row stride (floats)
#define NTHR 576

typedef unsigned long long ull;

__device__ float  g_z[(size_t)Bn * Cc * Tt * VP];
__device__ double g_psum[Cc * Bn];
__device__ double g_pss [Cc * Bn];
__device__ float  g_mean[Cc];
__device__ float  g_rstd[Cc];

// ---------------- smem layout (bytes) ----------------
// sW packed tiles [18 mt][6 kc][512B]    55296 @ 0
// sXk [4buf][96][40] fp16                 30720 @ 55296
// sYt [2][32][292] f32                    74752 @ 86016
// sA  [75][28]  f32                        8400 @ 160768
// sZB [96][28]  f32                       10752 @ 169168
// sAS [84]      f32                         336 @ 179920
#define SW_H 0
#define SXK  55296
#define SXK_ONE 7680
#define SYT  86016
#define SYT_ONE 37376
#define SA_  160768
#define SZB  169168
#define SAS  179920
#define SM_TOTAL 180256

__device__ __forceinline__ uint32_t smem_u32(const void* p) {
    uint32_t a;
    asm("{ .reg .u64 t; cvta.to.shared.u64 t, %1; cvt.u32.u64 %0, t; }" : "=r"(a) : "l"(p));
    return a;
}
__device__ __forceinline__ void fma2(ull &d, ull a, ull b) {
    asm("fma.rn.f32x2 %0, %1, %2, %0;" : "+l"(d) : "l"(a), "l"(b));
}
__device__ __forceinline__ ull dup2(float x) {
    ull r; asm("mov.b64 %0, {%1, %1};" : "=l"(r) : "f"(x)); return r;
}
__device__ __forceinline__ ull pack2(float lo, float hi) {
    ull r; asm("mov.b64 %0, {%1, %2};" : "=l"(r) : "f"(lo), "f"(hi)); return r;
}
__device__ __forceinline__ float lo2(ull v) { return __uint_as_float((unsigned)(v & 0xffffffffull)); }
__device__ __forceinline__ float hi2(ull v) { return __uint_as_float((unsigned)(v >> 32)); }

__device__ __forceinline__ void ldsm_x4(uint32_t* r, uint32_t addr) {
    asm volatile("ldmatrix.sync.aligned.m8n8.x4.shared.b16 {%0,%1,%2,%3}, [%4];"
        : "=r"(r[0]), "=r"(r[1]), "=r"(r[2]), "=r"(r[3]) : "r"(addr));
}
__device__ __forceinline__ void ldsm_x4_t(uint32_t* r, uint32_t addr) {
    asm volatile("ldmatrix.sync.aligned.m8n8.x4.trans.shared.b16 {%0,%1,%2,%3}, [%4];"
        : "=r"(r[0]), "=r"(r[1]), "=r"(r[2]), "=r"(r[3]) : "r"(addr));
}
__device__ __forceinline__ void mma_f16(float* d, const uint32_t* a, const uint32_t* b) {
    asm volatile("mma.sync.aligned.m16n8k16.row.col.f32.f16.f16.f32 "
        "{%0,%1,%2,%3}, {%4,%5,%6,%7}, {%8,%9}, {%0,%1,%2,%3};"
        : "+f"(d[0]), "+f"(d[1]), "+f"(d[2]), "+f"(d[3])
        : "r"(a[0]), "r"(a[1]), "r"(a[2]), "r"(a[3]), "r"(b[0]), "r"(b[1]));
}

// One SMALL unit: channels (2*cb, 2*cb+1), m-range [4*mt, 4*mt+4)
__device__ __forceinline__ void small_unit(const float* __restrict__ ybuf,
                                           const float* __restrict__ sA,
                                           const float* __restrict__ sZB,
                                           int b, int t, int u) {
    const int cb = u / 7;
    const int mt = u % 7;
    const int c0 = cb * 2;
    const int m0 = mt * 4;
    ull z0[4];
#pragma unroll
    for (int j = 0; j < 4; j++)
        z0[j] = pack2(sZB[c0 * VP + m0 + j], sZB[(c0 + 1) * VP + m0 + j]);
#pragma unroll
    for (int s = 0; s < Ss; s++) {
        const float* yrow = ybuf + s * Cc + c0;
        const float* arow = sA + s * (Vv * VP) + m0;
#pragma unroll 5
        for (int n = 0; n < Vv; n++) {
            ull yy = *(const ull*)(yrow);
            float4 av = *(const float4*)(arow);
            fma2(z0[0], yy, dup2(av.x)); fma2(z0[1], yy, dup2(av.y));
            fma2(z0[2], yy, dup2(av.z)); fma2(z0[3], yy, dup2(av.w));
            yrow += WROW;
            arow += VP;
        }
    }
    const size_t cstride = (size_t)Tt * VP;
    float* zb = g_z + ((size_t)(b * Cc + c0) * Tt + t) * VP + m0;
    float4 v;
    v.x = lo2(z0[0]); v.y = lo2(z0[1]); v.z = lo2(z0[2]); v.w = lo2(z0[3]);
    *(float4*)(zb) = v;
    v.x = hi2(z0[0]); v.y = hi2(z0[1]); v.z = hi2(z0[2]); v.w = hi2(z0[3]);
    *(float4*)(zb + cstride) = v;
}

// ---------------------------------------------------------------------------
// Pass 1 (t-pair iterations): per (b, 32-t tile). 576 threads / 18 warps.
// Per iteration (16 iters of t-pairs):
//   Phase A: warp w computes m-tile w for t AND t+1 (A-frags shared);
//            then stores prefetched x(t+2),x(t+3) into free buffers.
//   barrier
//   Phase B: 672 SMALL units (336 per t) over 576 threads.
//   barrier
// ---------------------------------------------------------------------------
__global__ void __launch_bounds__(NTHR, 1)
pass1_kernel(const float* __restrict__ x, const float* __restrict__ A,
             const float* __restrict__ W, const float* __restrict__ bias) {
    extern __shared__ char sm8[];
    const uint32_t smb = smem_u32(sm8);
    float* sYt = (float*)(sm8 + SYT);
    float* sA  = (float*)(sm8 + SA_);
    float* sZB = (float*)(sm8 + SZB);
    float* sAS = (float*)(sm8 + SAS);

    const int tid = threadIdx.x;
    const int t0  = blockIdx.x * TTc;
    const int b   = blockIdx.y;

    // ---- preamble: W fp16 into packed ldmatrix tiles ----
    for (int idx = tid; idx < Oo * CIN; idx += NTHR) {
        int o = idx / CIN, k = idx % CIN;
        __half h = __float2half(W[idx]);
        int mt = o >> 4, r16 = o & 15, kc = k >> 4, kk = k & 15;
        int off = (mt * 6 + kc) * 512 + (((kk >> 3) * 2 + (r16 >> 3)) * 128)
                + ((r16 & 7) * 16) + ((kk & 7) * 2);
        *(__half*)(sm8 + SW_H + off) = h;
    }
    // zero X buffers (pads v=25..39 stay zero)
    for (int idx = tid; idx < (4 * SXK_ONE) / 4; idx += NTHR)
        ((uint32_t*)(sm8 + SXK))[idx] = 0u;
    // A padded fp32
    for (int idx = tid; idx < Ss * Vv * VP; idx += NTHR) {
        int row = idx / VP, m = idx % VP;
        sA[idx] = (m < Vv) ? A[row * Vv + m] : 0.0f;
    }
    __syncthreads();
    // column sums of A per (s, m)
    if (tid < Ss * VP) {
        int s = tid / VP, m = tid % VP;
        float acc = 0.0f;
#pragma unroll
        for (int n = 0; n < Vv; n++) acc += sA[(s * Vv + n) * VP + m];
        sAS[tid] = acc;
    }
    __syncthreads();
    // zb[c][m] = sum_s bias[s*96+c] * sAS[s][m]
    for (int idx = tid; idx < Cc * VP; idx += NTHR) {
        int c = idx / VP, m = idx % VP;
        sZB[idx] = bias[c] * sAS[m] + bias[Cc + c] * sAS[VP + m]
                 + bias[2 * Cc + c] * sAS[2 * VP + m];
    }

    // per-thread x addressing (5 elements, 5*576 = 2880 >= 2400)
    int koff[5], soff[5];
#pragma unroll
    for (int r = 0; r < 5; r++) {
        int idx = tid + r * NTHR;
        int k = idx / Vv, v = idx - k * Vv;
        koff[r] = (b * CIN + k) * (Tt * Vv) + v;
        soff[r] = k * 40 + v;
    }
    // initial x(t0), x(t0+1) -> buffers 0, 1
#pragma unroll
    for (int j = 0; j < 2; j++) {
#pragma unroll
        for (int r = 0; r < 5; r++) {
            if (tid + r * NTHR < CIN * Vv) {
                float xv = x[koff[r] + (t0 + j) * Vv];
                *(__half*)(sm8 + SXK + j * SXK_ONE + soff[r] * 2) = __float2half(xv);
            }
        }
    }
    __syncthreads();

    // MMA mapping: 18 warps, 18 m-tiles, one each
    const int w    = tid >> 5;
    const int lane = tid & 31;
    const uint32_t m0t = w;
    const uint32_t blo = (((lane & 7) + (((lane >> 3) & 1) << 3)) * 40 + ((lane >> 4) << 3)) * 2;
    // D store mapping
    const int drow = lane >> 2;
    const int dcol = (lane & 3) * 2;

    const uint32_t swh = smb + SW_H;
    const uint32_t la  = lane * 16;

    for (int tt = 0; tt < TTc; tt += 2) {
        const int t = t0 + tt;
        const bool hn = (tt + 2 < TTc);

        // issue x(t+2), x(t+3) prefetch early
        float pf[10];
        if (hn) {
#pragma unroll
            for (int j = 0; j < 2; j++)
#pragma unroll
                for (int r = 0; r < 5; r++)
                    if (tid + r * NTHR < CIN * Vv)
                        pf[j * 5 + r] = x[koff[r] + (t + 2 + j) * Vv];
        }

        // ---- Phase A: two mini-GEMMs (t, t+1), one m-tile per warp ----
#pragma unroll
        for (int j = 0; j < 2; j++) {
            const uint32_t sxh = smb + SXK + ((tt + j) & 3) * SXK_ONE;
            float d0[4][4];
#pragma unroll
            for (int nt = 0; nt < 4; nt++)
#pragma unroll
                for (int q = 0; q < 4; q++) d0[nt][q] = 0.f;

#pragma unroll
            for (int kc = 0; kc < 6; kc++) {
                const uint32_t kbB = kc * 1280;   // 16 rows * 40 f16 * 2B

                uint32_t ah0[4];
                ldsm_x4(ah0, swh + (m0t * 6 + kc) * 512 + la);

                uint32_t bh[4][2], rr[4];
                ldsm_x4_t(rr, sxh + kbB + blo);
                bh[0][0]=rr[0]; bh[0][1]=rr[1]; bh[1][0]=rr[2]; bh[1][1]=rr[3];
                ldsm_x4_t(rr, sxh + kbB + blo + 32);   // v0 = 16
                bh[2][0]=rr[0]; bh[2][1]=rr[1]; bh[3][0]=rr[2]; bh[3][1]=rr[3];

#pragma unroll
                for (int nt = 0; nt < 4; nt++)
                    mma_f16(d0[nt], ah0, bh[nt]);
            }
            // D -> sYt[j][v][o]
            float* yb = sYt + j * (SYT_ONE / 4);
#pragma unroll
            for (int nt = 0; nt < 4; nt++) {
                float* p0 = yb + (nt * 8 + dcol) * WROW + m0t * 16 + drow;
                p0[0] = d0[nt][0]; p0[WROW] = d0[nt][1]; p0[8] = d0[nt][2]; p0[WROW + 8] = d0[nt][3];
            }
        }

        // store prefetched x(t+2), x(t+3) into their (free) buffers
        if (hn) {
#pragma unroll
            for (int j = 0; j < 2; j++) {
                char* bh8 = sm8 + SXK + ((tt + 2 + j) & 3) * SXK_ONE;
#pragma unroll
                for (int r = 0; r < 5; r++) {
                    if (tid + r * NTHR < CIN * Vv)
                        *(__half*)(bh8 + soff[r] * 2) = __float2half(pf[j * 5 + r]);
                }
            }
        }
        __syncthreads();   // sYt ready; x buffers written

        // ---- Phase B: 672 SMALL units over 576 threads ----
        {
            const float* yb0 = sYt;
            const float* yb1 = sYt + (SYT_ONE / 4);
            if (tid < 336) small_unit(yb0, sA, sZB, b, t, tid);
            else           small_unit(yb1, sA, sZB, b, t + 1, tid - 336);
            if (tid >= 480) small_unit(yb1, sA, sZB, b, t + 1, tid - 240);
        }
        __syncthreads();   // sYt consumed
    }
}

// ---------------------------------------------------------------------------
// Pass 2a/2b/3 (proven, unchanged)
// ---------------------------------------------------------------------------
__global__ void __launch_bounds__(256)
pass2a_kernel() {
    const int c = blockIdx.x;
    const int b = blockIdx.y;
    const int tid = threadIdx.x;
    __shared__ float sP[Tt * VP];
    __shared__ double red[512];

    const float* src = g_z + (size_t)(b * Cc + c) * Tt * VP;
    for (int i = tid; i < Tt * VP; i += 256) sP[i] = src[i];
    __syncthreads();

    double s = 0.0, q = 0.0;
    int t = tid / Vv, m = tid % Vv;
    for (int it = 0; it < 29; it++) {
        if (t < Tt) {
            float v = 0.0f;
#pragma unroll
            for (int k = -2; k <= 2; k++) {
                int tk = t + k;
                if (tk >= 0 && tk < Tt) v += sP[tk * VP + m];
            }
            v *= 0.2f;
            s += (double)v;
            q += (double)v * (double)v;
        }
        t += 10; m += 6;
        if (m >= Vv) { m -= Vv; t += 1; }
    }
    red[tid] = s; red[256 + tid] = q;
    __syncthreads();
    for (int s2 = 128; s2 > 0; s2 >>= 1) {
        if (tid < s2) {
            red[tid] += red[tid + s2];
            red[256 + tid] += red[256 + tid + s2];
        }
        __syncthreads();
    }
    if (tid == 0) {
        g_psum[c * Bn + b] = red[0];
        g_pss [c * Bn + b] = red[256];
    }
}

__global__ void __launch_bounds__(32)
pass2b_kernel() {
    const int c = blockIdx.x;
    const int lane = threadIdx.x;
    double s = g_psum[c * Bn + lane];
    double q = g_pss [c * Bn + lane];
#pragma unroll
    for (int o = 16; o > 0; o >>= 1) {
        s += __shfl_down_sync(0xffffffffu, s, o);
        q += __shfl_down_sync(0xffffffffu, q, o);
    }
    if (lane == 0) {
        const double N = (double)Bn * Tt * Vv;
        double mean = s / N;
        double var  = q / N - mean * mean;
        g_mean[c] = (float)mean;
        g_rstd[c] = (float)(1.0 / sqrt(var + 1e-5));
    }
}

__global__ void __launch_bounds__(256)
pass3_kernel(const float* __restrict__ gamma, const float* __restrict__ beta,
             float* __restrict__ out) {
    const int c = blockIdx.x;
    const int b = blockIdx.y;
    const int tid = threadIdx.x;
    __shared__ float sP[Tt * VP];

    const float* src = g_z + (size_t)(b * Cc + c) * Tt * VP;
    for (int i = tid; i < Tt * VP; i += 256) sP[i] = src[i];
    __syncthreads();

    const float mean = g_mean[c];
    const float rstd = g_rstd[c];
    const float sc = rstd * gamma[c];
    const float sh = beta[c] - mean * sc;

    float* dst = out + (size_t)(b * Cc + c) * Tt * Vv;
    int t = tid / Vv, m = tid % Vv;
    int i = tid;
    for (int it = 0; it < 29; it++) {
        if (t < Tt) {
            float v = 0.0f;
#pragma unroll
            for (int k = -2; k <= 2; k++) {
                int tk = t + k;
                if (tk >= 0 && tk < Tt) v += sP[tk * VP + m];
            }
            v *= 0.2f;
            float o = fmaf(v, sc, sh);
            dst[i] = fmaxf(o, 0.0f);
        }
        t += 10; m += 6; i += 256;
        if (m >= Vv) { m -= Vv; t += 1; }
    }
}

// ---------------------------------------------------------------------------
extern "C" void kernel_launch(void* const* d_in, const int* in_sizes, int n_in,
                              void* d_out, int out_size) {
    const float* x     = (const float*)d_in[0];
    const float* A     = (const float*)d_in[1];
    const float* W     = (const float*)d_in[2];
    const float* bias  = (const float*)d_in[3];
    const float* gamma = (const float*)d_in[4];
    const float* beta  = (const float*)d_in[5];
    float* out = (float*)d_out;

    cudaFuncSetAttribute(pass1_kernel, cudaFuncAttributeMaxDynamicSharedMemorySize, SM_TOTAL);

    pass1_kernel<<<dim3(NT, Bn), NTHR, SM_TOTAL>>>(x, A, W, bias);
    pass2a_kernel<<<dim3(Cc, Bn), 256>>>();
    pass2b_kernel<<<Cc, 32>>>();
    pass3_kernel<<<dim3(Cc, Bn), 256>>>(gamma, beta, out);
}

// round 15
// speedup vs baseline: 1.0339x; 1.0339x over previous
#include <cuda_runtime.h>
#include <cuda_fp16.h>
#include <math.h>
#include <stdint.h>

// Problem constants
#define Bn 32
#define CIN 96
#define Tt 288
#define Vv 25
#define Ss 3
#define Cc 96
#define Oo 288
#define VP 28
#define TTc 32
#define NT 9
#define WROW 292         // sYt row stride (floats)
#define NTHR 576

typedef unsigned long long ull;

__device__ __half g_z[(size_t)Bn * Cc * Tt * VP];   // fp16 z scratch
__device__ double g_psum[Cc * Bn];
__device__ double g_pss [Cc * Bn];
__device__ float  g_mean[Cc];
__device__ float  g_rstd[Cc];

// ---------------- smem layout (bytes) ----------------
#define SW_H 0              // packed W tiles: 55296
#define SXK  55296          // X: [2buf][96][40] fp16 = 15360
#define SXK_ONE 7680
#define SYT  70656          // sYt: [32][292] f32 = 37376
#define SA_  108032         // A padded: 8400
#define SZB  116432         // bias-fold: 10752
#define SAS  127184         // A col sums: 336
#define SM_TOTAL 127520

__device__ __forceinline__ uint32_t smem_u32(const void* p) {
    uint32_t a;
    asm("{ .reg .u64 t; cvta.to.shared.u64 t, %1; cvt.u32.u64 %0, t; }" : "=r"(a) : "l"(p));
    return a;
}
__device__ __forceinline__ void fma2(ull &d, ull a, ull b) {
    asm("fma.rn.f32x2 %0, %1, %2, %0;" : "+l"(d) : "l"(a), "l"(b));
}
__device__ __forceinline__ ull dup2(float x) {
    ull r; asm("mov.b64 %0, {%1, %1};" : "=l"(r) : "f"(x)); return r;
}
__device__ __forceinline__ ull pack2(float lo, float hi) {
    ull r; asm("mov.b64 %0, {%1, %2};" : "=l"(r) : "f"(lo), "f"(hi)); return r;
}
__device__ __forceinline__ float lo2(ull v) { return __uint_as_float((unsigned)(v & 0xffffffffull)); }
__device__ __forceinline__ float hi2(ull v) { return __uint_as_float((unsigned)(v >> 32)); }

__device__ __forceinline__ void ldsm_x4(uint32_t* r, uint32_t addr) {
    asm volatile("ldmatrix.sync.aligned.m8n8.x4.shared.b16 {%0,%1,%2,%3}, [%4];"
        : "=r"(r[0]), "=r"(r[1]), "=r"(r[2]), "=r"(r[3]) : "r"(addr));
}
__device__ __forceinline__ void ldsm_x4_t(uint32_t* r, uint32_t addr) {
    asm volatile("ldmatrix.sync.aligned.m8n8.x4.trans.shared.b16 {%0,%1,%2,%3}, [%4];"
        : "=r"(r[0]), "=r"(r[1]), "=r"(r[2]), "=r"(r[3]) : "r"(addr));
}
__device__ __forceinline__ void mma_f16(float* d, const uint32_t* a, const uint32_t* b) {
    asm volatile("mma.sync.aligned.m16n8k16.row.col.f32.f16.f16.f32 "
        "{%0,%1,%2,%3}, {%4,%5,%6,%7}, {%8,%9}, {%0,%1,%2,%3};"
        : "+f"(d[0]), "+f"(d[1]), "+f"(d[2]), "+f"(d[3])
        : "r"(a[0]), "r"(a[1]), "r"(a[2]), "r"(a[3]), "r"(b[0]), "r"(b[1]));
}

// One SMALL unit: channels (2*cb, 2*cb+1), m-range [4*mt, 4*mt+4); fp16 z store
__device__ __forceinline__ void small_unit(const float* __restrict__ sYt,
                                           const float* __restrict__ sA,
                                           const float* __restrict__ sZB,
                                           int b, int t, int u) {
    const int cb = u / 7;
    const int mt = u % 7;
    const int c0 = cb * 2;
    const int m0 = mt * 4;
    ull z0[4];
#pragma unroll
    for (int j = 0; j < 4; j++)
        z0[j] = pack2(sZB[c0 * VP + m0 + j], sZB[(c0 + 1) * VP + m0 + j]);
#pragma unroll
    for (int s = 0; s < Ss; s++) {
        const float* yrow = sYt + s * Cc + c0;
        const float* arow = sA + s * (Vv * VP) + m0;
#pragma unroll 5
        for (int n = 0; n < Vv; n++) {
            ull yy = *(const ull*)(yrow);
            float4 av = *(const float4*)(arow);
            fma2(z0[0], yy, dup2(av.x)); fma2(z0[1], yy, dup2(av.y));
            fma2(z0[2], yy, dup2(av.z)); fma2(z0[3], yy, dup2(av.w));
            yrow += WROW;
            arow += VP;
        }
    }
    const size_t cstride = (size_t)Tt * VP;
    __half* zb = g_z + ((size_t)(b * Cc + c0) * Tt + t) * VP + m0;
    {
        __half2 p01 = __floats2half2_rn(lo2(z0[0]), lo2(z0[1]));
        __half2 p23 = __floats2half2_rn(lo2(z0[2]), lo2(z0[3]));
        uint2 v; v.x = *(uint32_t*)&p01; v.y = *(uint32_t*)&p23;
        *(uint2*)(zb) = v;
    }
    {
        __half2 p01 = __floats2half2_rn(hi2(z0[0]), hi2(z0[1]));
        __half2 p23 = __floats2half2_rn(hi2(z0[2]), hi2(z0[3]));
        uint2 v; v.x = *(uint32_t*)&p01; v.y = *(uint32_t*)&p23;
        *(uint2*)(zb + cstride) = v;
    }
}

// ---------------------------------------------------------------------------
// Pass 1 (R13 structure, frozen): per (b, 32-t tile). 576 threads / 18 warps.
// ---------------------------------------------------------------------------
__global__ void __launch_bounds__(NTHR, 1)
pass1_kernel(const float* __restrict__ x, const float* __restrict__ A,
             const float* __restrict__ W, const float* __restrict__ bias) {
    extern __shared__ char sm8[];
    const uint32_t smb = smem_u32(sm8);
    float* sYt = (float*)(sm8 + SYT);
    float* sA  = (float*)(sm8 + SA_);
    float* sZB = (float*)(sm8 + SZB);
    float* sAS = (float*)(sm8 + SAS);

    const int tid = threadIdx.x;
    const int t0  = blockIdx.x * TTc;
    const int b   = blockIdx.y;

    // ---- preamble: W fp16 into packed ldmatrix tiles ----
    for (int idx = tid; idx < Oo * CIN; idx += NTHR) {
        int o = idx / CIN, k = idx % CIN;
        __half h = __float2half(W[idx]);
        int mt = o >> 4, r16 = o & 15, kc = k >> 4, kk = k & 15;
        int off = (mt * 6 + kc) * 512 + (((kk >> 3) * 2 + (r16 >> 3)) * 128)
                + ((r16 & 7) * 16) + ((kk & 7) * 2);
        *(__half*)(sm8 + SW_H + off) = h;
    }
    for (int idx = tid; idx < (2 * SXK_ONE) / 4; idx += NTHR)
        ((uint32_t*)(sm8 + SXK))[idx] = 0u;
    for (int idx = tid; idx < Ss * Vv * VP; idx += NTHR) {
        int row = idx / VP, m = idx % VP;
        sA[idx] = (m < Vv) ? A[row * Vv + m] : 0.0f;
    }
    __syncthreads();
    if (tid < Ss * VP) {
        int s = tid / VP, m = tid % VP;
        float acc = 0.0f;
#pragma unroll
        for (int n = 0; n < Vv; n++) acc += sA[(s * Vv + n) * VP + m];
        sAS[tid] = acc;
    }
    __syncthreads();
    for (int idx = tid; idx < Cc * VP; idx += NTHR) {
        int c = idx / VP, m = idx % VP;
        sZB[idx] = bias[c] * sAS[m] + bias[Cc + c] * sAS[VP + m]
                 + bias[2 * Cc + c] * sAS[2 * VP + m];
    }

    int koff[5], soff[5];
#pragma unroll
    for (int r = 0; r < 5; r++) {
        int idx = tid + r * NTHR;
        int k = idx / Vv, v = idx - k * Vv;
        koff[r] = (b * CIN + k) * (Tt * Vv) + v;
        soff[r] = k * 40 + v;
    }
#pragma unroll
    for (int r = 0; r < 5; r++) {
        if (tid + r * NTHR < CIN * Vv) {
            float xv = x[koff[r] + t0 * Vv];
            *(__half*)(sm8 + SXK + soff[r] * 2) = __float2half(xv);
        }
    }
    __syncthreads();

    const int w    = tid >> 5;
    const int lane = tid & 31;
    const uint32_t m0t = w;
    const uint32_t blo = (((lane & 7) + (((lane >> 3) & 1) << 3)) * 40 + ((lane >> 4) << 3)) * 2;
    const int drow = lane >> 2;
    const int dcol = (lane & 3) * 2;

    const uint32_t swh = smb + SW_H;
    const uint32_t la  = lane * 16;

    for (int tt = 0; tt < TTc; tt++) {
        const int t   = t0 + tt;
        const int cur = tt & 1;
        const bool hn = (tt + 1 < TTc);

        float pf[5];
        if (hn) {
#pragma unroll
            for (int r = 0; r < 5; r++)
                if (tid + r * NTHR < CIN * Vv) pf[r] = x[koff[r] + (t + 1) * Vv];
        }

        // ---- Phase A: BIG via mma.sync fp16, 1 tile per warp ----
        {
            const uint32_t sxh = smb + SXK + cur * SXK_ONE;
            float d0[4][4];
#pragma unroll
            for (int nt = 0; nt < 4; nt++)
#pragma unroll
                for (int q = 0; q < 4; q++) d0[nt][q] = 0.f;

#pragma unroll
            for (int kc = 0; kc < 6; kc++) {
                const uint32_t kbB = kc * 1280;

                uint32_t ah0[4];
                ldsm_x4(ah0, swh + (m0t * 6 + kc) * 512 + la);

                uint32_t bh[4][2], rr[4];
                ldsm_x4_t(rr, sxh + kbB + blo);
                bh[0][0]=rr[0]; bh[0][1]=rr[1]; bh[1][0]=rr[2]; bh[1][1]=rr[3];
                ldsm_x4_t(rr, sxh + kbB + blo + 32);
                bh[2][0]=rr[0]; bh[2][1]=rr[1]; bh[3][0]=rr[2]; bh[3][1]=rr[3];

#pragma unroll
                for (int nt = 0; nt < 4; nt++)
                    mma_f16(d0[nt], ah0, bh[nt]);
            }
#pragma unroll
            for (int nt = 0; nt < 4; nt++) {
                float* p0 = sYt + (nt * 8 + dcol) * WROW + m0t * 16 + drow;
                p0[0] = d0[nt][0]; p0[WROW] = d0[nt][1]; p0[8] = d0[nt][2]; p0[WROW + 8] = d0[nt][3];
            }
        }
        __syncthreads();

        // ---- Phase B: store x(t+1); SMALL one unit per tid<336 ----
        if (hn) {
            char* bh8 = sm8 + SXK + (cur ^ 1) * SXK_ONE;
#pragma unroll
            for (int r = 0; r < 5; r++) {
                if (tid + r * NTHR < CIN * Vv)
                    *(__half*)(bh8 + soff[r] * 2) = __float2half(pf[r]);
            }
        }

        if (tid < 336) small_unit(sYt, sA, sZB, b, t, tid);

        __syncthreads();
    }
}

// ---------------------------------------------------------------------------
// Pass 2a: per-(c,b) plane partial BN stats over windowed z (fp16 loads).
// ---------------------------------------------------------------------------
__global__ void __launch_bounds__(256)
pass2a_kernel() {
    const int c = blockIdx.x;
    const int b = blockIdx.y;
    const int tid = threadIdx.x;
    __shared__ float sP[Tt * VP];
    __shared__ double red[512];

    const __half2* src = (const __half2*)(g_z + (size_t)(b * Cc + c) * Tt * VP);
    for (int i = tid; i < (Tt * VP) / 2; i += 256) {
        float2 f = __half22float2(src[i]);
        sP[2 * i]     = f.x;
        sP[2 * i + 1] = f.y;
    }
    __syncthreads();

    double s = 0.0, q = 0.0;
    int t = tid / Vv, m = tid % Vv;
    for (int it = 0; it < 29; it++) {
        if (t < Tt) {
            float v = 0.0f;
#pragma unroll
            for (int k = -2; k <= 2; k++) {
                int tk = t + k;
                if (tk >= 0 && tk < Tt) v += sP[tk * VP + m];
            }
            v *= 0.2f;
            s += (double)v;
            q += (double)v * (double)v;
        }
        t += 10; m += 6;
        if (m >= Vv) { m -= Vv; t += 1; }
    }
    red[tid] = s; red[256 + tid] = q;
    __syncthreads();
    for (int s2 = 128; s2 > 0; s2 >>= 1) {
        if (tid < s2) {
            red[tid] += red[tid + s2];
            red[256 + tid] += red[256 + tid + s2];
        }
        __syncthreads();
    }
    if (tid == 0) {
        g_psum[c * Bn + b] = red[0];
        g_pss [c * Bn + b] = red[256];
    }
}

__global__ void __launch_bounds__(32)
pass2b_kernel() {
    const int c = blockIdx.x;
    const int lane = threadIdx.x;
    double s = g_psum[c * Bn + lane];
    double q = g_pss [c * Bn + lane];
#pragma unroll
    for (int o = 16; o > 0; o >>= 1) {
        s += __shfl_down_sync(0xffffffffu, s, o);
        q += __shfl_down_sync(0xffffffffu, q, o);
    }
    if (lane == 0) {
        const double N = (double)Bn * Tt * Vv;
        double mean = s / N;
        double var  = q / N - mean * mean;
        g_mean[c] = (float)mean;
        g_rstd[c] = (float)(1.0 / sqrt(var + 1e-5));
    }
}

// ---------------------------------------------------------------------------
// Pass 3: window-avg + normalize + affine + relu (fp16 z loads)
// ---------------------------------------------------------------------------
__global__ void __launch_bounds__(256)
pass3_kernel(const float* __restrict__ gamma, const float* __restrict__ beta,
             float* __restrict__ out) {
    const int c = blockIdx.x;
    const int b = blockIdx.y;
    const int tid = threadIdx.x;
    __shared__ float sP[Tt * VP];

    const __half2* src = (const __half2*)(g_z + (size_t)(b * Cc + c) * Tt * VP);
    for (int i = tid; i < (Tt * VP) / 2; i += 256) {
        float2 f = __half22float2(src[i]);
        sP[2 * i]     = f.x;
        sP[2 * i + 1] = f.y;
    }
    __syncthreads();

    const float mean = g_mean[c];
    const float rstd = g_rstd[c];
    const float sc = rstd * gamma[c];
    const float sh = beta[c] - mean * sc;

    float* dst = out + (size_t)(b * Cc + c) * Tt * Vv;
    int t = tid / Vv, m = tid % Vv;
    int i = tid;
    for (int it = 0; it < 29; it++) {
        if (t < Tt) {
            float v = 0.0f;
#pragma unroll
            for (int k = -2; k <= 2; k++) {
                int tk = t + k;
                if (tk >= 0 && tk < Tt) v += sP[tk * VP + m];
            }
            v *= 0.2f;
            float o = fmaf(v, sc, sh);
            dst[i] = fmaxf(o, 0.0f);
        }
        t += 10; m += 6; i += 256;
        if (m >= Vv) { m -= Vv; t += 1; }
    }
}

// ---------------------------------------------------------------------------
extern "C" void kernel_launch(void* const* d_in, const int* in_sizes, int n_in,
                              void* d_out, int out_size) {
    const float* x     = (const float*)d_in[0];
    const float* A     = (const float*)d_in[1];
    const float* W     = (const float*)d_in[2];
    const float* bias  = (const float*)d_in[3];
    const float* gamma = (const float*)d_in[4];
    const float* beta  = (const float*)d_in[5];
    float* out = (float*)d_out;

    cudaFuncSetAttribute(pass1_kernel, cudaFuncAttributeMaxDynamicSharedMemorySize, SM_TOTAL);

    pass1_kernel<<<dim3(NT, Bn), NTHR, SM_TOTAL>>>(x, A, W, bias);
    pass2a_kernel<<<dim3(Cc, Bn), 256>>>();
    pass2b_kernel<<<Cc, 32>>>();
    pass3_kernel<<<dim3(Cc, Bn), 256>>>(gamma, beta, out);
}

// round 16
// speedup vs baseline: 1.1075x; 1.0711x over previous
#include <cuda_runtime.h>
#include <cuda_fp16.h>
#include <math.h>
#include <stdint.h>

// Problem constants
#define Bn 32
#define CIN 96
#define Tt 288
#define Vv 25
#define Ss 3
#define Cc 96
#define Oo 288
#define VP 28
#define TTc 32
#define NT 9
#define YROWH 296        // sYt row stride (halfs)
#define NTHR 576

typedef unsigned long long ull;

__device__ __half g_z[(size_t)Bn * Cc * Tt * VP];   // fp16 z scratch
__device__ double g_psum[Cc * Bn];
__device__ double g_pss [Cc * Bn];
__device__ float  g_mean[Cc];
__device__ float  g_rstd[Cc];

// ---------------- smem layout (bytes) ----------------
// sW packed tiles [18 mt][6 kc][512B]    55296 @ 0
// sXk [2buf][96][40] fp16                 15360 @ 55296
// sYt [32][296] fp16                      18944 @ 70656
// sA  [75][28]  f32                        8400 @ 89600
// sZB [96][28]  f32                       10752 @ 98000
// sAS [84]      f32                         336 @ 108752
#define SW_H 0
#define SXK  55296
#define SXK_ONE 7680
#define SYT  70656
#define SA_  89600
#define SZB  98000
#define SAS  108752
#define SM_TOTAL 109088

__device__ __forceinline__ uint32_t smem_u32(const void* p) {
    uint32_t a;
    asm("{ .reg .u64 t; cvta.to.shared.u64 t, %1; cvt.u32.u64 %0, t; }" : "=r"(a) : "l"(p));
    return a;
}
__device__ __forceinline__ void fma2(ull &d, ull a, ull b) {
    asm("fma.rn.f32x2 %0, %1, %2, %0;" : "+l"(d) : "l"(a), "l"(b));
}
__device__ __forceinline__ ull dup2(float x) {
    ull r; asm("mov.b64 %0, {%1, %1};" : "=l"(r) : "f"(x)); return r;
}
__device__ __forceinline__ ull pack2(float lo, float hi) {
    ull r; asm("mov.b64 %0, {%1, %2};" : "=l"(r) : "f"(lo), "f"(hi)); return r;
}
__device__ __forceinline__ float lo2(ull v) { return __uint_as_float((unsigned)(v & 0xffffffffull)); }
__device__ __forceinline__ float hi2(ull v) { return __uint_as_float((unsigned)(v >> 32)); }

__device__ __forceinline__ void ldsm_x4(uint32_t* r, uint32_t addr) {
    asm volatile("ldmatrix.sync.aligned.m8n8.x4.shared.b16 {%0,%1,%2,%3}, [%4];"
        : "=r"(r[0]), "=r"(r[1]), "=r"(r[2]), "=r"(r[3]) : "r"(addr));
}
__device__ __forceinline__ void ldsm_x4_t(uint32_t* r, uint32_t addr) {
    asm volatile("ldmatrix.sync.aligned.m8n8.x4.trans.shared.b16 {%0,%1,%2,%3}, [%4];"
        : "=r"(r[0]), "=r"(r[1]), "=r"(r[2]), "=r"(r[3]) : "r"(addr));
}
__device__ __forceinline__ void mma_f16(float* d, const uint32_t* a, const uint32_t* b) {
    asm volatile("mma.sync.aligned.m16n8k16.row.col.f32.f16.f16.f32 "
        "{%0,%1,%2,%3}, {%4,%5,%6,%7}, {%8,%9}, {%0,%1,%2,%3};"
        : "+f"(d[0]), "+f"(d[1]), "+f"(d[2]), "+f"(d[3])
        : "r"(a[0]), "r"(a[1]), "r"(a[2]), "r"(a[3]), "r"(b[0]), "r"(b[1]));
}

// One SMALL unit: channels (2*cb, 2*cb+1), m-range [4*mt, 4*mt+4); fp16 y + fp16 z
__device__ __forceinline__ void small_unit(const char* __restrict__ sYtB,
                                           const float* __restrict__ sA,
                                           const float* __restrict__ sZB,
                                           int b, int t, int u) {
    const int cb = u / 7;
    const int mt = u % 7;
    const int c0 = cb * 2;
    const int m0 = mt * 4;
    ull z0[4];
#pragma unroll
    for (int j = 0; j < 4; j++)
        z0[j] = pack2(sZB[c0 * VP + m0 + j], sZB[(c0 + 1) * VP + m0 + j]);
#pragma unroll
    for (int s = 0; s < Ss; s++) {
        const char* yrow = sYtB + (s * Cc + c0) * 2;
        const float* arow = sA + s * (Vv * VP) + m0;
#pragma unroll 5
        for (int n = 0; n < Vv; n++) {
            __half2 h2 = *(const __half2*)(yrow);
            float2 yf = __half22float2(h2);
            ull yy = pack2(yf.x, yf.y);
            float4 av = *(const float4*)(arow);
            fma2(z0[0], yy, dup2(av.x)); fma2(z0[1], yy, dup2(av.y));
            fma2(z0[2], yy, dup2(av.z)); fma2(z0[3], yy, dup2(av.w));
            yrow += YROWH * 2;
            arow += VP;
        }
    }
    const size_t cstride = (size_t)Tt * VP;
    __half* zb = g_z + ((size_t)(b * Cc + c0) * Tt + t) * VP + m0;
    {
        __half2 p01 = __floats2half2_rn(lo2(z0[0]), lo2(z0[1]));
        __half2 p23 = __floats2half2_rn(lo2(z0[2]), lo2(z0[3]));
        uint2 v; v.x = *(uint32_t*)&p01; v.y = *(uint32_t*)&p23;
        *(uint2*)(zb) = v;
    }
    {
        __half2 p01 = __floats2half2_rn(hi2(z0[0]), hi2(z0[1]));
        __half2 p23 = __floats2half2_rn(hi2(z0[2]), hi2(z0[3]));
        uint2 v; v.x = *(uint32_t*)&p01; v.y = *(uint32_t*)&p23;
        *(uint2*)(zb + cstride) = v;
    }
}

// ---------------------------------------------------------------------------
// Pass 1 (R13 skeleton; fp16 sYt; 2 CTAs/SM): per (b, 32-t tile). 576 thr.
// ---------------------------------------------------------------------------
__global__ void __launch_bounds__(NTHR, 2)
pass1_kernel(const float* __restrict__ x, const float* __restrict__ A,
             const float* __restrict__ W, const float* __restrict__ bias) {
    extern __shared__ char sm8[];
    const uint32_t smb = smem_u32(sm8);
    float* sA  = (float*)(sm8 + SA_);
    float* sZB = (float*)(sm8 + SZB);
    float* sAS = (float*)(sm8 + SAS);

    const int tid = threadIdx.x;
    const int t0  = blockIdx.x * TTc;
    const int b   = blockIdx.y;

    // ---- preamble: W fp16 into packed ldmatrix tiles ----
    for (int idx = tid; idx < Oo * CIN; idx += NTHR) {
        int o = idx / CIN, k = idx % CIN;
        __half h = __float2half(W[idx]);
        int mt = o >> 4, r16 = o & 15, kc = k >> 4, kk = k & 15;
        int off = (mt * 6 + kc) * 512 + (((kk >> 3) * 2 + (r16 >> 3)) * 128)
                + ((r16 & 7) * 16) + ((kk & 7) * 2);
        *(__half*)(sm8 + SW_H + off) = h;
    }
    for (int idx = tid; idx < (2 * SXK_ONE) / 4; idx += NTHR)
        ((uint32_t*)(sm8 + SXK))[idx] = 0u;
    for (int idx = tid; idx < Ss * Vv * VP; idx += NTHR) {
        int row = idx / VP, m = idx % VP;
        sA[idx] = (m < Vv) ? A[row * Vv + m] : 0.0f;
    }
    __syncthreads();
    if (tid < Ss * VP) {
        int s = tid / VP, m = tid % VP;
        float acc = 0.0f;
#pragma unroll
        for (int n = 0; n < Vv; n++) acc += sA[(s * Vv + n) * VP + m];
        sAS[tid] = acc;
    }
    __syncthreads();
    for (int idx = tid; idx < Cc * VP; idx += NTHR) {
        int c = idx / VP, m = idx % VP;
        sZB[idx] = bias[c] * sAS[m] + bias[Cc + c] * sAS[VP + m]
                 + bias[2 * Cc + c] * sAS[2 * VP + m];
    }
    // initial x(t0) -> buf 0 (addresses computed inline)
#pragma unroll
    for (int r = 0; r < 5; r++) {
        int idx = tid + r * NTHR;
        if (idx < CIN * Vv) {
            int k = idx / Vv, v = idx - k * Vv;
            float xv = x[(b * CIN + k) * (Tt * Vv) + t0 * Vv + v];
            *(__half*)(sm8 + SXK + (k * 40 + v) * 2) = __float2half(xv);
        }
    }
    __syncthreads();

    // MMA mapping: 18 warps, 18 m-tiles, one each
    const int w    = tid >> 5;
    const int lane = tid & 31;
    const uint32_t m0t = w;
    const uint32_t blo = (((lane & 7) + (((lane >> 3) & 1) << 3)) * 40 + ((lane >> 4) << 3)) * 2;
    const int drow = lane >> 2;
    const int dcol = (lane & 3) * 2;

    const uint32_t swh = smb + SW_H;
    const uint32_t la  = lane * 16;

    for (int tt = 0; tt < TTc; tt++) {
        const int t   = t0 + tt;
        const int cur = tt & 1;
        const bool hn = (tt + 1 < TTc);

        // issue x(t+1) prefetch (indices recomputed, only pf lives across A)
        float pf[5];
        if (hn) {
#pragma unroll
            for (int r = 0; r < 5; r++) {
                int idx = tid + r * NTHR;
                if (idx < CIN * Vv) {
                    int k = idx / Vv, v = idx - k * Vv;
                    pf[r] = x[(b * CIN + k) * (Tt * Vv) + (t + 1) * Vv + v];
                }
            }
        }

        // ---- Phase A: BIG via mma.sync fp16, 1 tile per warp ----
        {
            const uint32_t sxh = smb + SXK + cur * SXK_ONE;
            float d0[4][4];
#pragma unroll
            for (int nt = 0; nt < 4; nt++)
#pragma unroll
                for (int q = 0; q < 4; q++) d0[nt][q] = 0.f;

#pragma unroll
            for (int kc = 0; kc < 6; kc++) {
                const uint32_t kbB = kc * 1280;

                uint32_t ah0[4];
                ldsm_x4(ah0, swh + (m0t * 6 + kc) * 512 + la);

                uint32_t bh[4][2], rr[4];
                ldsm_x4_t(rr, sxh + kbB + blo);
                bh[0][0]=rr[0]; bh[0][1]=rr[1]; bh[1][0]=rr[2]; bh[1][1]=rr[3];
                ldsm_x4_t(rr, sxh + kbB + blo + 32);
                bh[2][0]=rr[0]; bh[2][1]=rr[1]; bh[3][0]=rr[2]; bh[3][1]=rr[3];

#pragma unroll
                for (int nt = 0; nt < 4; nt++)
                    mma_f16(d0[nt], ah0, bh[nt]);
            }
            // D -> sYt[v][o] fp16
            __half* yb = (__half*)(sm8 + SYT);
#pragma unroll
            for (int nt = 0; nt < 4; nt++) {
                __half* p0 = yb + (nt * 8 + dcol) * YROWH + m0t * 16 + drow;
                p0[0]         = __float2half(d0[nt][0]);
                p0[YROWH]     = __float2half(d0[nt][1]);
                p0[8]         = __float2half(d0[nt][2]);
                p0[YROWH + 8] = __float2half(d0[nt][3]);
            }
        }
        __syncthreads();

        // ---- Phase B: store x(t+1); SMALL one unit per tid<336 ----
        if (hn) {
            char* bh8 = sm8 + SXK + (cur ^ 1) * SXK_ONE;
#pragma unroll
            for (int r = 0; r < 5; r++) {
                int idx = tid + r * NTHR;
                if (idx < CIN * Vv) {
                    int k = idx / Vv, v = idx - k * Vv;
                    *(__half*)(bh8 + (k * 40 + v) * 2) = __float2half(pf[r]);
                }
            }
        }

        if (tid < 336) small_unit(sm8 + SYT, sA, sZB, b, t, tid);

        __syncthreads();
    }
}

// ---------------------------------------------------------------------------
// Pass 2a: per-(c,b) plane partial BN stats over windowed z (fp16 loads).
// ---------------------------------------------------------------------------
__global__ void __launch_bounds__(256)
pass2a_kernel() {
    const int c = blockIdx.x;
    const int b = blockIdx.y;
    const int tid = threadIdx.x;
    __shared__ float sP[Tt * VP];
    __shared__ double red[512];

    const __half2* src = (const __half2*)(g_z + (size_t)(b * Cc + c) * Tt * VP);
    for (int i = tid; i < (Tt * VP) / 2; i += 256) {
        float2 f = __half22float2(src[i]);
        sP[2 * i]     = f.x;
        sP[2 * i + 1] = f.y;
    }
    __syncthreads();

    double s = 0.0, q = 0.0;
    int t = tid / Vv, m = tid % Vv;
    for (int it = 0; it < 29; it++) {
        if (t < Tt) {
            float v = 0.0f;
#pragma unroll
            for (int k = -2; k <= 2; k++) {
                int tk = t + k;
                if (tk >= 0 && tk < Tt) v += sP[tk * VP + m];
            }
            v *= 0.2f;
            s += (double)v;
            q += (double)v * (double)v;
        }
        t += 10; m += 6;
        if (m >= Vv) { m -= Vv; t += 1; }
    }
    red[tid] = s; red[256 + tid] = q;
    __syncthreads();
    for (int s2 = 128; s2 > 0; s2 >>= 1) {
        if (tid < s2) {
            red[tid] += red[tid + s2];
            red[256 + tid] += red[256 + tid + s2];
        }
        __syncthreads();
    }
    if (tid == 0) {
        g_psum[c * Bn + b] = red[0];
        g_pss [c * Bn + b] = red[256];
    }
}

__global__ void __launch_bounds__(32)
pass2b_kernel() {
    const int c = blockIdx.x;
    const int lane = threadIdx.x;
    double s = g_psum[c * Bn + lane];
    double q = g_pss [c * Bn + lane];
#pragma unroll
    for (int o = 16; o > 0; o >>= 1) {
        s += __shfl_down_sync(0xffffffffu, s, o);
        q += __shfl_down_sync(0xffffffffu, q, o);
    }
    if (lane == 0) {
        const double N = (double)Bn * Tt * Vv;
        double mean = s / N;
        double var  = q / N - mean * mean;
        g_mean[c] = (float)mean;
        g_rstd[c] = (float)(1.0 / sqrt(var + 1e-5));
    }
}

// ---------------------------------------------------------------------------
// Pass 3: window-avg + normalize + affine + relu (fp16 z loads)
// ---------------------------------------------------------------------------
__global__ void __launch_bounds__(256)
pass3_kernel(const float* __restrict__ gamma, const float* __restrict__ beta,
             float* __restrict__ out) {
    const int c = blockIdx.x;
    const int b = blockIdx.y;
    const int tid = threadIdx.x;
    __shared__ float sP[Tt * VP];

    const __half2* src = (const __half2*)(g_z + (size_t)(b * Cc + c) * Tt * VP);
    for (int i = tid; i < (Tt * VP) / 2; i += 256) {
        float2 f = __half22float2(src[i]);
        sP[2 * i]     = f.x;
        sP[2 * i + 1] = f.y;
    }
    __syncthreads();

    const float mean = g_mean[c];
    const float rstd = g_rstd[c];
    const float sc = rstd * gamma[c];
    const float sh = beta[c] - mean * sc;

    float* dst = out + (size_t)(b * Cc + c) * Tt * Vv;
    int t = tid / Vv, m = tid % Vv;
    int i = tid;
    for (int it = 0; it < 29; it++) {
        if (t < Tt) {
            float v = 0.0f;
#pragma unroll
            for (int k = -2; k <= 2; k++) {
                int tk = t + k;
                if (tk >= 0 && tk < Tt) v += sP[tk * VP + m];
            }
            v *= 0.2f;
            float o = fmaf(v, sc, sh);
            dst[i] = fmaxf(o, 0.0f);
        }
        t += 10; m += 6; i += 256;
        if (m >= Vv) { m -= Vv; t += 1; }
    }
}

// ---------------------------------------------------------------------------
extern "C" void kernel_launch(void* const* d_in, const int* in_sizes, int n_in,
                              void* d_out, int out_size) {
    const float* x     = (const float*)d_in[0];
    const float* A     = (const float*)d_in[1];
    const float* W     = (const float*)d_in[2];
    const float* bias  = (const float*)d_in[3];
    const float* gamma = (const float*)d_in[4];
    const float* beta  = (const float*)d_in[5];
    float* out = (float*)d_out;

    cudaFuncSetAttribute(pass1_kernel, cudaFuncAttributeMaxDynamicSharedMemorySize, SM_TOTAL);

    pass1_kernel<<<dim3(NT, Bn), NTHR, SM_TOTAL>>>(x, A, W, bias);
    pass2a_kernel<<<dim3(Cc, Bn), 256>>>();
    pass2b_kernel<<<Cc, 32>>>();
    pass3_kernel<<<dim3(Cc, Bn), 256>>>(gamma, beta, out);
}

// round 17
// speedup vs baseline: 1.4809x; 1.3372x over previous
#include <cuda_runtime.h>
#include <cuda_fp16.h>
#include <math.h>
#include <stdint.h>

// Problem constants
#define Bn 32
#define CIN 96
#define Tt 288
#define Vv 25
#define Ss 3
#define Cc 96
#define Oo 288
#define VP 28
#define TTc 32
#define NT 9
#define YROWH 296        // sYt row stride (halfs)
#define NTHR 576

typedef unsigned long long ull;

__device__ __half g_z[(size_t)Bn * Cc * Tt * VP];   // fp16 z scratch
__device__ double g_psum[Cc * Bn];
__device__ double g_pss [Cc * Bn];
__device__ float  g_mean[Cc];
__device__ float  g_rstd[Cc];

// ---------------- smem layout (bytes) ----------------
// sW packed tiles [18 mt][6 kc][512B]    55296 @ 0
// sXk [2buf][96][40] fp16                 15360 @ 55296
// sYt [32][296] fp16                      18944 @ 70656
// sAF A' mma B-frag table                  5120 @ 89600
// sZB [96][28]  f32                       10752 @ 94720
// sAS [84]      f32                         336 @ 105472
#define SW_H 0
#define SXK  55296
#define SXK_ONE 7680
#define SYT  70656
#define SAF  89600
#define SZB  94720
#define SAS  105472
#define SM_TOTAL 105808

__device__ __forceinline__ uint32_t smem_u32(const void* p) {
    uint32_t a;
    asm("{ .reg .u64 t; cvta.to.shared.u64 t, %1; cvt.u32.u64 %0, t; }" : "=r"(a) : "l"(p));
    return a;
}
__device__ __forceinline__ void ldsm_x4(uint32_t* r, uint32_t addr) {
    asm volatile("ldmatrix.sync.aligned.m8n8.x4.shared.b16 {%0,%1,%2,%3}, [%4];"
        : "=r"(r[0]), "=r"(r[1]), "=r"(r[2]), "=r"(r[3]) : "r"(addr));
}
__device__ __forceinline__ void ldsm_x4_t(uint32_t* r, uint32_t addr) {
    asm volatile("ldmatrix.sync.aligned.m8n8.x4.trans.shared.b16 {%0,%1,%2,%3}, [%4];"
        : "=r"(r[0]), "=r"(r[1]), "=r"(r[2]), "=r"(r[3]) : "r"(addr));
}
__device__ __forceinline__ void mma_f16(float* d, const uint32_t* a, const uint32_t* b) {
    asm volatile("mma.sync.aligned.m16n8k16.row.col.f32.f16.f16.f32 "
        "{%0,%1,%2,%3}, {%4,%5,%6,%7}, {%8,%9}, {%0,%1,%2,%3};"
        : "+f"(d[0]), "+f"(d[1]), "+f"(d[2]), "+f"(d[3])
        : "r"(a[0]), "r"(a[1]), "r"(a[2]), "r"(a[3]), "r"(b[0]), "r"(b[1]));
}

// ---------------------------------------------------------------------------
// Pass 1: per (b, 32-t tile). 576 threads / 18 warps, 2 CTAs/SM.
// Phase A: Y = W16*X16 via mma.sync (18 warps, 1 m-tile each) -> sYt fp16.
// Phase B: x(t+1) store (all); SMALL as MMA on warps 0..5:
//          z[96][28] = Y'[96][80] @ A'[80][32] + biasfold, fp16 -> g_z.
// ---------------------------------------------------------------------------
__global__ void __launch_bounds__(NTHR, 2)
pass1_kernel(const float* __restrict__ x, const float* __restrict__ A,
             const float* __restrict__ W, const float* __restrict__ bias) {
    extern __shared__ char sm8[];
    const uint32_t smb = smem_u32(sm8);
    float* sZB = (float*)(sm8 + SZB);
    float* sAS = (float*)(sm8 + SAS);

    const int tid = threadIdx.x;
    const int t0  = blockIdx.x * TTc;
    const int b   = blockIdx.y;

    // ---- stage 1: W pack, X pad-zero, sAS, sAF ----
    for (int idx = tid; idx < Oo * CIN; idx += NTHR) {
        int o = idx / CIN, k = idx % CIN;
        __half h = __float2half(W[idx]);
        int mt = o >> 4, r16 = o & 15, kc = k >> 4, kk = k & 15;
        int off = (mt * 6 + kc) * 512 + (((kk >> 3) * 2 + (r16 >> 3)) * 128)
                + ((r16 & 7) * 16) + ((kk & 7) * 2);
        *(__half*)(sm8 + SW_H + off) = h;
    }
    // zero only X pad region (v=25..39) of both buffers
    for (int idx = tid; idx < 2 * CIN * 15; idx += NTHR) {
        int buf = idx / (CIN * 15);
        int r = idx % (CIN * 15);
        int k = r / 15, v = 25 + r % 15;
        *(__half*)(sm8 + SXK + buf * SXK_ONE + (k * 40 + v) * 2) = __float2half(0.0f);
    }
    // sAS[s][m] = sum_n A[sn][m]  (A index: (s*25+n)*25+m = sn*25+m)
    if (tid < Ss * VP) {
        int s = tid / VP, m = tid % VP;
        float acc = 0.0f;
        if (m < Vv) {
#pragma unroll
            for (int n = 0; n < Vv; n++) acc += A[(s * Vv + n) * Vv + m];
        }
        sAS[tid] = acc;
    }
    // sAF: pre-baked mma B-fragments of A' (fp16), [kc][nt][lane] -> uint2
    for (int idx = tid; idx < 640; idx += NTHR) {
        int lane2 = idx & 31;
        int rest = idx >> 5;
        int kc = rest / 4, nt = rest % 4;
        int m_g = nt * 8 + lane2 / 4;            // N dim (m), 0..31
        int k0 = kc * 16 + (lane2 & 3) * 2;      // K dim (sn) base
        __half hv[4];
#pragma unroll
        for (int r = 0; r < 2; r++)
#pragma unroll
            for (int j = 0; j < 2; j++) {
                int sn = k0 + r * 8 + j;
                float val = (sn < Ss * Vv && m_g < Vv) ? A[sn * Vv + m_g] : 0.0f;
                hv[r * 2 + j] = __float2half(val);
            }
        __half2 p0 = __halves2half2(hv[0], hv[1]);
        __half2 p1 = __halves2half2(hv[2], hv[3]);
        uint2 e;
        e.x = *(uint32_t*)&p0; e.y = *(uint32_t*)&p1;
        *(uint2*)(sm8 + SAF + idx * 8) = e;
    }
    __syncthreads();

    // ---- stage 2: sZB, x(t0) ----
    for (int idx = tid; idx < Cc * VP; idx += NTHR) {
        int c = idx / VP, m = idx % VP;
        sZB[idx] = bias[c] * sAS[m] + bias[Cc + c] * sAS[VP + m]
                 + bias[2 * Cc + c] * sAS[2 * VP + m];
    }
#pragma unroll
    for (int r = 0; r < 5; r++) {
        int idx = tid + r * NTHR;
        if (idx < CIN * Vv) {
            int k = idx / Vv, v = idx - k * Vv;
            float xv = x[(b * CIN + k) * (Tt * Vv) + t0 * Vv + v];
            *(__half*)(sm8 + SXK + (k * 40 + v) * 2) = __float2half(xv);
        }
    }
    __syncthreads();

    // mappings
    const int w    = tid >> 5;
    const int lane = tid & 31;
    const uint32_t m0t = w;
    const uint32_t blo = (((lane & 7) + (((lane >> 3) & 1) << 3)) * 40 + ((lane >> 4) << 3)) * 2;
    const int drow = lane >> 2;
    const int dcol = (lane & 3) * 2;
    const uint32_t swh = smb + SW_H;
    const uint32_t la  = lane * 16;

    // SMALL-MMA: per-lane y' row addresses (constant across t), warps 0..5
    uint32_t yaddr[5];
    {
        int klocal = (lane & 7) + ((lane >> 4) << 3);
        int coff   = ((lane >> 3) & 1) * 8;
#pragma unroll
        for (int kc = 0; kc < 5; kc++) {
            int sn = kc * 16 + klocal;
            int s = sn / Vv, n = sn % Vv;
            yaddr[kc] = smb + SYT + (uint32_t)((n * YROWH + s * Cc + w * 16 + coff) * 2);
        }
    }

    for (int tt = 0; tt < TTc; tt++) {
        const int t   = t0 + tt;
        const int cur = tt & 1;
        const bool hn = (tt + 1 < TTc);

        // issue x(t+1) prefetch
        float pf[5];
        if (hn) {
#pragma unroll
            for (int r = 0; r < 5; r++) {
                int idx = tid + r * NTHR;
                if (idx < CIN * Vv) {
                    int k = idx / Vv, v = idx - k * Vv;
                    pf[r] = x[(b * CIN + k) * (Tt * Vv) + (t + 1) * Vv + v];
                }
            }
        }

        // ---- Phase A: BIG via mma.sync fp16, 1 tile per warp ----
        {
            const uint32_t sxh = smb + SXK + cur * SXK_ONE;
            float d0[4][4];
#pragma unroll
            for (int nt = 0; nt < 4; nt++)
#pragma unroll
                for (int q = 0; q < 4; q++) d0[nt][q] = 0.f;

#pragma unroll
            for (int kc = 0; kc < 6; kc++) {
                const uint32_t kbB = kc * 1280;
                uint32_t ah0[4];
                ldsm_x4(ah0, swh + (m0t * 6 + kc) * 512 + la);

                uint32_t bh[4][2], rr[4];
                ldsm_x4_t(rr, sxh + kbB + blo);
                bh[0][0]=rr[0]; bh[0][1]=rr[1]; bh[1][0]=rr[2]; bh[1][1]=rr[3];
                ldsm_x4_t(rr, sxh + kbB + blo + 32);
                bh[2][0]=rr[0]; bh[2][1]=rr[1]; bh[3][0]=rr[2]; bh[3][1]=rr[3];

#pragma unroll
                for (int nt = 0; nt < 4; nt++)
                    mma_f16(d0[nt], ah0, bh[nt]);
            }
            // D -> sYt[v][o] fp16
            __half* yb = (__half*)(sm8 + SYT);
#pragma unroll
            for (int nt = 0; nt < 4; nt++) {
                __half* p0 = yb + (nt * 8 + dcol) * YROWH + m0t * 16 + drow;
                p0[0]         = __float2half(d0[nt][0]);
                p0[YROWH]     = __float2half(d0[nt][1]);
                p0[8]         = __float2half(d0[nt][2]);
                p0[YROWH + 8] = __float2half(d0[nt][3]);
            }
        }
        __syncthreads();   // sYt ready; sXk[nxt] free

        // ---- Phase B: x(t+1) store (all); SMALL-MMA on warps 0..5 ----
        if (hn) {
            char* bh8 = sm8 + SXK + (cur ^ 1) * SXK_ONE;
#pragma unroll
            for (int r = 0; r < 5; r++) {
                int idx = tid + r * NTHR;
                if (idx < CIN * Vv) {
                    int k = idx / Vv, v = idx - k * Vv;
                    *(__half*)(bh8 + (k * 40 + v) * 2) = __float2half(pf[r]);
                }
            }
        }

        if (w < 6) {
            float d[4][4];
#pragma unroll
            for (int nt = 0; nt < 4; nt++)
#pragma unroll
                for (int q = 0; q < 4; q++) d[nt][q] = 0.f;

#pragma unroll
            for (int kc = 0; kc < 5; kc++) {
                uint32_t ya[4];
                ldsm_x4_t(ya, yaddr[kc]);
#pragma unroll
                for (int nt = 0; nt < 4; nt++) {
                    uint2 bf = *(const uint2*)(sm8 + SAF + (((kc * 4 + nt) * 32) + lane) * 8);
                    mma_f16(d[nt], ya, (const uint32_t*)&bf);
                }
            }
            // epilogue: + bias-fold, fp16, store to g_z
            const int c0 = w * 16 + drow;
            const size_t zb0 = ((size_t)(b * Cc + c0) * Tt + t) * VP;
            const size_t zb1 = ((size_t)(b * Cc + c0 + 8) * Tt + t) * VP;
#pragma unroll
            for (int nt = 0; nt < 4; nt++) {
                int m0 = nt * 8 + dcol;
                if (m0 < 27) {
                    float2 z0 = *(const float2*)&sZB[c0 * VP + m0];
                    float2 z1 = *(const float2*)&sZB[(c0 + 8) * VP + m0];
                    __half2 h0 = __floats2half2_rn(d[nt][0] + z0.x, d[nt][1] + z0.y);
                    __half2 h1 = __floats2half2_rn(d[nt][2] + z1.x, d[nt][3] + z1.y);
                    *(__half2*)(g_z + zb0 + m0) = h0;
                    *(__half2*)(g_z + zb1 + m0) = h1;
                }
            }
        }
        __syncthreads();   // sYt consumed; sXk[nxt] written
    }
}

// ---------------------------------------------------------------------------
// Pass 2a: per-(c,b) plane partial BN stats over windowed z (fp16 loads).
// ---------------------------------------------------------------------------
__global__ void __launch_bounds__(256)
pass2a_kernel() {
    const int c = blockIdx.x;
    const int b = blockIdx.y;
    const int tid = threadIdx.x;
    __shared__ float sP[Tt * VP];
    __shared__ double red[512];

    const __half2* src = (const __half2*)(g_z + (size_t)(b * Cc + c) * Tt * VP);
    for (int i = tid; i < (Tt * VP) / 2; i += 256) {
        float2 f = __half22float2(src[i]);
        sP[2 * i]     = f.x;
        sP[2 * i + 1] = f.y;
    }
    __syncthreads();

    double s = 0.0, q = 0.0;
    int t = tid / Vv, m = tid % Vv;
    for (int it = 0; it < 29; it++) {
        if (t < Tt) {
            float v = 0.0f;
#pragma unroll
            for (int k = -2; k <= 2; k++) {
                int tk = t + k;
                if (tk >= 0 && tk < Tt) v += sP[tk * VP + m];
            }
            v *= 0.2f;
            s += (double)v;
            q += (double)v * (double)v;
        }
        t += 10; m += 6;
        if (m >= Vv) { m -= Vv; t += 1; }
    }
    red[tid] = s; red[256 + tid] = q;
    __syncthreads();
    for (int s2 = 128; s2 > 0; s2 >>= 1) {
        if (tid < s2) {
            red[tid] += red[tid + s2];
            red[256 + tid] += red[256 + tid + s2];
        }
        __syncthreads();
    }
    if (tid == 0) {
        g_psum[c * Bn + b] = red[0];
        g_pss [c * Bn + b] = red[256];
    }
}

__global__ void __launch_bounds__(32)
pass2b_kernel() {
    const int c = blockIdx.x;
    const int lane = threadIdx.x;
    double s = g_psum[c * Bn + lane];
    double q = g_pss [c * Bn + lane];
#pragma unroll
    for (int o = 16; o > 0; o >>= 1) {
        s += __shfl_down_sync(0xffffffffu, s, o);
        q += __shfl_down_sync(0xffffffffu, q, o);
    }
    if (lane == 0) {
        const double N = (double)Bn * Tt * Vv;
        double mean = s / N;
        double var  = q / N - mean * mean;
        g_mean[c] = (float)mean;
        g_rstd[c] = (float)(1.0 / sqrt(var + 1e-5));
    }
}

// ---------------------------------------------------------------------------
// Pass 3: window-avg + normalize + affine + relu (fp16 z loads)
// ---------------------------------------------------------------------------
__global__ void __launch_bounds__(256)
pass3_kernel(const float* __restrict__ gamma, const float* __restrict__ beta,
             float* __restrict__ out) {
    const int c = blockIdx.x;
    const int b = blockIdx.y;
    const int tid = threadIdx.x;
    __shared__ float sP[Tt * VP];

    const __half2* src = (const __half2*)(g_z + (size_t)(b * Cc + c) * Tt * VP);
    for (int i = tid; i < (Tt * VP) / 2; i += 256) {
        float2 f = __half22float2(src[i]);
        sP[2 * i]     = f.x;
        sP[2 * i + 1] = f.y;
    }
    __syncthreads();

    const float mean = g_mean[c];
    const float rstd = g_rstd[c];
    const float sc = rstd * gamma[c];
    const float sh = beta[c] - mean * sc;

    float* dst = out + (size_t)(b * Cc + c) * Tt * Vv;
    int t = tid / Vv, m = tid % Vv;
    int i = tid;
    for (int it = 0; it < 29; it++) {
        if (t < Tt) {
            float v = 0.0f;
#pragma unroll
            for (int k = -2; k <= 2; k++) {
                int tk = t + k;
                if (tk >= 0 && tk < Tt) v += sP[tk * VP + m];
            }
            v *= 0.2f;
            float o = fmaf(v, sc, sh);
            dst[i] = fmaxf(o, 0.0f);
        }
        t += 10; m += 6; i += 256;
        if (m >= Vv) { m -= Vv; t += 1; }
    }
}

// ---------------------------------------------------------------------------
extern "C" void kernel_launch(void* const* d_in, const int* in_sizes, int n_in,
                              void* d_out, int out_size) {
    const float* x     = (const float*)d_in[0];
    const float* A     = (const float*)d_in[1];
    const float* W     = (const float*)d_in[2];
    const float* bias  = (const float*)d_in[3];
    const float* gamma = (const float*)d_in[4];
    const float* beta  = (const float*)d_in[5];
    float* out = (float*)d_out;

    cudaFuncSetAttribute(pass1_kernel, cudaFuncAttributeMaxDynamicSharedMemorySize, SM_TOTAL);

    pass1_kernel<<<dim3(NT, Bn), NTHR, SM_TOTAL>>>(x, A, W, bias);
    pass2a_kernel<<<dim3(Cc, Bn), 256>>>();
    pass2b_kernel<<<Cc, 32>>>();
    pass3_kernel<<<dim3(Cc, Bn), 256>>>(gamma, beta, out);
}